// round 15
// baseline (speedup 1.0000x reference)
#include <cuda_runtime.h>
#include <cuda_fp16.h>
#include <math.h>
#include <stdint.h>

#define D_IN 1024
#define D_H  512
#define NBINS 10
#define MAXB 65536

// ---------------- scratch (no allocations allowed) ----------------
__device__ unsigned int g_min_enc[2];
__device__ unsigned int g_max_enc[2];
__device__ int          g_hist[2][NBINS];
__device__ float        g_wglobal[2];
__device__ __align__(16) __half g_W0h[D_H * D_IN];   // blended W0, fp16
__device__ __align__(16) float g_W1b[D_H];
__device__ __align__(16) float g_partial[2 * MAXB];

// ---------------- PTX helpers ----------------
__device__ __forceinline__ uint32_t smem_u32(const void* p) {
    uint32_t a;
    asm("{ .reg .u64 t; cvta.to.shared.u64 t, %1; cvt.u32.u64 %0, t; }"
        : "=r"(a) : "l"(p));
    return a;
}
__device__ __forceinline__ void cp16(uint32_t dst, const void* src) {
    asm volatile("cp.async.cg.shared.global [%0], [%1], 16;"
                 :: "r"(dst), "l"(src) : "memory");
}
__device__ __forceinline__ void cp_commit() {
    asm volatile("cp.async.commit_group;" ::: "memory");
}
template <int N>
__device__ __forceinline__ void cp_wait() {
    asm volatile("cp.async.wait_group %0;" :: "n"(N) : "memory");
}
__device__ __forceinline__ void ldsm4(uint32_t* r, uint32_t addr) {
    asm volatile("ldmatrix.sync.aligned.m8n8.x4.shared.b16 {%0,%1,%2,%3}, [%4];"
                 : "=r"(r[0]), "=r"(r[1]), "=r"(r[2]), "=r"(r[3]) : "r"(addr));
}
__device__ __forceinline__ void mma_f16(float* c, const uint32_t* a,
                                        const uint32_t* b) {
    asm volatile(
        "mma.sync.aligned.m16n8k16.row.col.f32.f16.f16.f32 "
        "{%0,%1,%2,%3}, {%4,%5,%6,%7}, {%8,%9}, {%0,%1,%2,%3};"
        : "+f"(c[0]), "+f"(c[1]), "+f"(c[2]), "+f"(c[3])
        : "r"(a[0]), "r"(a[1]), "r"(a[2]), "r"(a[3]), "r"(b[0]), "r"(b[1]));
}
__device__ __forceinline__ void sts128(uint32_t addr, uint32_t a, uint32_t b,
                                       uint32_t c, uint32_t d) {
    asm volatile("st.shared.v4.b32 [%0], {%1,%2,%3,%4};"
                 :: "r"(addr), "r"(a), "r"(b), "r"(c), "r"(d) : "memory");
}

// ---------------- entropy path (exact jnp half-open bins) ----------
__device__ __forceinline__ unsigned int enc_f(float f) {
    unsigned int u = __float_as_uint(f);
    return (u & 0x80000000u) ? ~u : (u | 0x80000000u);
}
__device__ __forceinline__ float dec_f(unsigned int u) {
    u = (u & 0x80000000u) ? (u ^ 0x80000000u) : ~u;
    return __uint_as_float(u);
}

__global__ void init_kernel() {
    int t = threadIdx.x;
    if (t < 2) { g_min_enc[t] = 0xFFFFFFFFu; g_max_enc[t] = 0u; }
    if (t < 2 * NBINS) g_hist[t / NBINS][t % NBINS] = 0;
}

__global__ void minmax2_kernel(const float* __restrict__ w0,
                               const float* __restrict__ g0, int n4) {
    int slot = blockIdx.y;
    const float4* p = (const float4*)(slot ? g0 : w0);
    unsigned int mn = 0xFFFFFFFFu, mx = 0u;
    int stride = gridDim.x * blockDim.x;
    for (int i = blockIdx.x * blockDim.x + threadIdx.x; i < n4; i += stride) {
        float4 v = p[i];
        unsigned int e0 = enc_f(v.x), e1 = enc_f(v.y);
        unsigned int e2 = enc_f(v.z), e3 = enc_f(v.w);
        mn = min(min(mn, e0), min(e1, min(e2, e3)));
        mx = max(max(mx, e0), max(e1, max(e2, e3)));
    }
#pragma unroll
    for (int o = 16; o; o >>= 1) {
        mn = min(mn, __shfl_down_sync(0xffffffffu, mn, o));
        mx = max(mx, __shfl_down_sync(0xffffffffu, mx, o));
    }
    __shared__ unsigned int smn[8], smx[8];
    int w = threadIdx.x >> 5, l = threadIdx.x & 31;
    if (l == 0) { smn[w] = mn; smx[w] = mx; }
    __syncthreads();
    if (threadIdx.x == 0) {
        int nw = blockDim.x >> 5;
        for (int i = 1; i < nw; i++) { mn = min(mn, smn[i]); mx = max(mx, smx[i]); }
        atomicMin(&g_min_enc[slot], mn);
        atomicMax(&g_max_enc[slot], mx);
    }
}

__global__ void hist2_kernel(const float* __restrict__ w0,
                             const float* __restrict__ g0, int n4) {
    int slot = blockIdx.y;
    const float4* p = (const float4*)(slot ? g0 : w0);
    __shared__ int sh[NBINS];
    if (threadIdx.x < NBINS) sh[threadIdx.x] = 0;
    __syncthreads();
    float lo = dec_f(g_min_enc[slot]);
    float hi = dec_f(g_max_enc[slot]);
    float scale = __fdiv_rn(__fsub_rn(hi, lo), 10.0f);
    float inv = 1.0f / scale;
    int stride = gridDim.x * blockDim.x;
    for (int i = blockIdx.x * blockDim.x + threadIdx.x; i < n4; i += stride) {
        float4 q = p[i];
        float vv[4] = {q.x, q.y, q.z, q.w};
#pragma unroll
        for (int e = 0; e < 4; e++) {
            float v = vv[e];
            int bc = (int)((v - lo) * inv);
            int b0 = max(bc - 1, 0), b1 = min(bc + 1, NBINS - 1);
            for (int b = b0; b <= b1; b++) {
                float lower = __fadd_rn(lo, __fmul_rn((float)b, scale));
                float upper = __fadd_rn(lo, __fmul_rn((float)(b + 1), scale));
                if (v >= lower && v < upper) { atomicAdd(&sh[b], 1); break; }
            }
        }
    }
    __syncthreads();
    if (threadIdx.x < NBINS) atomicAdd(&g_hist[slot][threadIdx.x], sh[threadIdx.x]);
}

__global__ void scalar_kernel(const float* __restrict__ w1,
                              const float* __restrict__ g1) {
    __shared__ unsigned int smn[2], smx[2];
    __shared__ int shist[2][NBINS];
    __shared__ float sH[2];
    int tid = threadIdx.x;  // 256 threads
    if (tid < 2) { smn[tid] = 0xFFFFFFFFu; smx[tid] = 0u; }
    if (tid < 2 * NBINS) shist[tid / NBINS][tid % NBINS] = 0;
    __syncthreads();
    const float* arr[2] = {w1, g1};
    for (int a = 0; a < 2; a++) {
        float v0 = arr[a][tid], v1 = arr[a][tid + 256];
        unsigned int mn = min(enc_f(v0), enc_f(v1));
        unsigned int mx = max(enc_f(v0), enc_f(v1));
#pragma unroll
        for (int o = 16; o; o >>= 1) {
            mn = min(mn, __shfl_down_sync(0xffffffffu, mn, o));
            mx = max(mx, __shfl_down_sync(0xffffffffu, mx, o));
        }
        if ((tid & 31) == 0) { atomicMin(&smn[a], mn); atomicMax(&smx[a], mx); }
    }
    __syncthreads();
    for (int a = 0; a < 2; a++) {
        float lo = dec_f(smn[a]), hi = dec_f(smx[a]);
        float scale = __fdiv_rn(__fsub_rn(hi, lo), 10.0f);
#pragma unroll
        for (int e = 0; e < 2; e++) {
            float v = arr[a][tid + e * 256];
#pragma unroll
            for (int b = 0; b < NBINS; b++) {
                float lower = __fadd_rn(lo, __fmul_rn((float)b, scale));
                float upper = __fadd_rn(lo, __fmul_rn((float)(b + 1), scale));
                if (v >= lower && v < upper) { atomicAdd(&shist[a][b], 1); break; }
            }
        }
    }
    __syncthreads();
    if (tid == 0) {
        const float API = 0.12732395447351627f;  // 0.4/pi
        float Hbig[2];
        for (int a = 0; a < 2; a++) {
            float h = 0.f;
            for (int b = 0; b < NBINS; b++) {
                float pp = (float)g_hist[a][b] / (float)(D_H * D_IN);
                if (pp > 0.f) h += -pp * logf(pp);
            }
            Hbig[a] = h;
        }
        g_wglobal[0] = API * atanf(500.0f * (Hbig[0] - Hbig[1])) + 0.5f;
        for (int a = 0; a < 2; a++) {
            float h = 0.f;
            for (int b = 0; b < NBINS; b++) {
                float pp = (float)shist[a][b] / (float)D_H;
                if (pp > 0.f) h += -pp * logf(pp);
            }
            sH[a] = h;
        }
        g_wglobal[1] = API * atanf(500.0f * (sH[0] - sH[1])) + 0.5f;
    }
}

__device__ __forceinline__ float blend_one(float base, float graft, float d, float wg) {
    float wl = 1.0f / (1.0f + expf(-d));
    float wb = wg * (1.0f - expf(-wg * wl));
    float og = 1.0f - wg;
    float wgf = og * (1.0f - expf(-og * (1.0f - wl)));
    float s = 1.0f / (1.0f + expf(wgf - wb));  // softmax pair == sigmoid(diff)
    return base * s + graft * (1.0f - s);
}

// ---------- w0 blend via fp16 mma (validated R9) -------------------------
#define WBROWB 80
__global__ __launch_bounds__(256) void w0_blend_mma_kernel(
    const float* __restrict__ w0, const float* __restrict__ g0,
    const float* __restrict__ p0) {
    __shared__ __align__(16) __half sA[2][64 * 40];
    __shared__ __align__(16) __half sB[2][128 * 40];
    const int tid = threadIdx.x;
    const int wid = tid >> 5, lane = tid & 31;
    const int wm = wid >> 2;
    const int wn = wid & 3;
    const int rowBase = blockIdx.y * 64;
    const int colBase = blockIdx.x * 128;
    const uint32_t sAu = smem_u32(&sA[0][0]);
    const uint32_t sBu = smem_u32(&sB[0][0]);

    const int ar = tid >> 2, agr = tid & 3;
    const int br = tid >> 1, bh = tid & 1;

    float4 aw[2], ag[2], bp[4];
    float acc[2][4][4] = {};

    auto lds = [&](int it) {
        if (it < 32) {
            const float* wr = w0 + (size_t)(rowBase + ar) * D_IN + it * 32 + agr * 8;
            const float* gr = g0 + (size_t)(rowBase + ar) * D_IN + it * 32 + agr * 8;
            const float* pr = p0 + (size_t)(colBase + br) * D_IN + it * 32 + bh * 16;
#pragma unroll
            for (int j = 0; j < 2; j++) {
                aw[j] = *(const float4*)(wr + j * 4);
                ag[j] = *(const float4*)(gr + j * 4);
            }
#pragma unroll
            for (int j = 0; j < 4; j++) bp[j] = *(const float4*)(pr + j * 4);
        }
    };
    auto sts = [&](int it) {
        if (it >= 32) return;
        int st = it & 1;
        uint32_t wa[4];
#pragma unroll
        for (int j = 0; j < 2; j++) {
            float d0 = fabsf(aw[j].x - ag[j].x), d1 = fabsf(aw[j].y - ag[j].y);
            float d2 = fabsf(aw[j].z - ag[j].z), d3 = fabsf(aw[j].w - ag[j].w);
            unsigned short h0 = __half_as_ushort(__float2half_rn(d0));
            unsigned short h1 = __half_as_ushort(__float2half_rn(d1));
            unsigned short h2 = __half_as_ushort(__float2half_rn(d2));
            unsigned short h3 = __half_as_ushort(__float2half_rn(d3));
            wa[2 * j]     = (uint32_t)h0 | ((uint32_t)h1 << 16);
            wa[2 * j + 1] = (uint32_t)h2 | ((uint32_t)h3 << 16);
        }
        sts128(sAu + (uint32_t)(st * 5120 + ar * WBROWB + agr * 16),
               wa[0], wa[1], wa[2], wa[3]);
        uint32_t bw[8];
#pragma unroll
        for (int j = 0; j < 4; j++) {
            unsigned short h0 = __half_as_ushort(__float2half_rn(bp[j].x));
            unsigned short h1 = __half_as_ushort(__float2half_rn(bp[j].y));
            unsigned short h2 = __half_as_ushort(__float2half_rn(bp[j].z));
            unsigned short h3 = __half_as_ushort(__float2half_rn(bp[j].w));
            bw[2 * j]     = (uint32_t)h0 | ((uint32_t)h1 << 16);
            bw[2 * j + 1] = (uint32_t)h2 | ((uint32_t)h3 << 16);
        }
        uint32_t bb = sBu + (uint32_t)(st * 10240 + br * WBROWB + bh * 32);
        sts128(bb,      bw[0], bw[1], bw[2], bw[3]);
        sts128(bb + 16, bw[4], bw[5], bw[6], bw[7]);
    };

    lds(0); sts(0); lds(1);
    for (int it = 0; it < 32; ++it) {
        const int st = it & 1;
        __syncthreads();
        sts(it + 1);
        lds(it + 2);
#pragma unroll
        for (int ks = 0; ks < 2; ks++) {
            uint32_t a[2][4], b[2][4];
#pragma unroll
            for (int mi = 0; mi < 2; mi++) {
                uint32_t ro = (uint32_t)(st * 5120 +
                    (wm * 32 + mi * 16 + (lane & 15)) * WBROWB +
                    ks * 32 + (lane >> 4) * 16);
                ldsm4(a[mi], sAu + ro);
            }
#pragma unroll
            for (int p = 0; p < 2; p++) {
                uint32_t bo = (uint32_t)(st * 10240 +
                    (wn * 32 + p * 16 + (lane >> 4) * 8 + (lane & 7)) * WBROWB +
                    ks * 32 + ((lane >> 3) & 1) * 16);
                ldsm4(b[p], sBu + bo);
            }
#pragma unroll
            for (int mi = 0; mi < 2; mi++)
#pragma unroll
                for (int p = 0; p < 2; p++) {
                    mma_f16(acc[mi][2 * p],     a[mi], &b[p][0]);
                    mma_f16(acc[mi][2 * p + 1], a[mi], &b[p][2]);
                }
        }
    }

    float wg = g_wglobal[0];
#pragma unroll
    for (int mi = 0; mi < 2; mi++)
#pragma unroll
        for (int ni = 0; ni < 4; ni++) {
            int col = colBase + wn * 32 + ni * 8 + 2 * (lane & 3);
#pragma unroll
            for (int rh = 0; rh < 2; rh++) {
                int o = rowBase + wm * 32 + mi * 16 + (lane >> 2) + rh * 8;
                size_t base = (size_t)o * D_IN + col;
                float v0 = blend_one(w0[base], g0[base], acc[mi][ni][2 * rh], wg);
                float v1 = blend_one(w0[base + 1], g0[base + 1],
                                     acc[mi][ni][2 * rh + 1], wg);
                __half2 h2v = __floats2half2_rn(v0, v1);
                *(__half2*)(g_W0h + base) = h2v;
            }
        }
}

__global__ void w1_blend_kernel(const float* __restrict__ w1,
                                const float* __restrict__ g1,
                                const float* __restrict__ p1) {
    int i = blockIdx.x * blockDim.x + threadIdx.x;
    if (i >= D_H) return;
    float d = 0.f;
    for (int k = 0; k < D_H; k++) d += fabsf(w1[k] - g1[k]) * p1[i * D_H + k];
    g_W1b[i] = blend_one(w1[i], g1[i], d, g_wglobal[1]);
}

// ---------------- main GEMM: 256 thr, 128x256 tile, GBK=64, k32 batches ---
#define GBM 128
#define GBN 256
#define GBK 64
#define KITER (D_IN / GBK)   // 16
#define ROWB 144             // 64 fp16 = 128B + 16B pad

#define A_OFF(st) ((uint32_t)((st) * 18432))
#define B_OFF(st) ((uint32_t)(36864 + (st) * 36864))
#define RED_OFF 147456u

__global__ __launch_bounds__(256, 1) void gemm_mma_kernel(
    const float* __restrict__ x, const float* __restrict__ b0, int Brows) {
    extern __shared__ char dsm[];
    const uint32_t sb = smem_u32(dsm);
    float* red = (float*)(dsm + RED_OFF);  // [128][4]

    const int tid = threadIdx.x;
    const int wid = tid >> 5, lane = tid & 31;
    const int wm = wid >> 2;       // 0..1 -> 64-row warp tile
    const int wn = wid & 3;        // 0..3 -> 64-col warp tile
    const int colBlk = blockIdx.x;            // 0..1
    const int rowBase = blockIdx.y * GBM;
    const int nBase = colBlk * GBN;

    // A: 2 threads/row, each 32 floats
    const int ar = tid >> 1, ah = tid & 1;
    const float* xrow = x + (size_t)(rowBase + ar) * D_IN + ah * 32;

    float acc[4][8][4] = {};
    float4 xr[8];

    auto load_B = [&](int it, int st) {
        if (it < KITER) {
            const __half* srcH = g_W0h + (size_t)nBase * D_IN + it * GBK;
#pragma unroll
            for (int i = 0; i < 8; i++) {
                int q = tid + i * 256;          // 0..2047
                int r = q >> 3, g = q & 7;      // 256 rows x 8 granules
                uint32_t doff = (uint32_t)(r * ROWB + g * 16);
                cp16(sb + B_OFF(st) + doff, srcH + (size_t)r * D_IN + g * 8);
            }
        }
        cp_commit();
    };

    auto lds_x = [&](int it) {
        if (it < KITER) {
#pragma unroll
            for (int j = 0; j < 8; j++)
                xr[j] = *(const float4*)(xrow + it * GBK + j * 4);
        }
    };

    auto sts_A = [&](int it) {
        if (it >= KITER) return;
        int st = it & 1;
        uint32_t base = (uint32_t)(ar * ROWB + ah * 64);
#pragma unroll
        for (int h = 0; h < 2; h++) {
            uint32_t hw[8];
#pragma unroll
            for (int j = 0; j < 4; j++) {
                float4 v = xr[h * 4 + j];
                unsigned short h0 = __half_as_ushort(__float2half_rn(v.x));
                unsigned short h1 = __half_as_ushort(__float2half_rn(v.y));
                unsigned short h2 = __half_as_ushort(__float2half_rn(v.z));
                unsigned short h3 = __half_as_ushort(__float2half_rn(v.w));
                hw[2 * j]     = (uint32_t)h0 | ((uint32_t)h1 << 16);
                hw[2 * j + 1] = (uint32_t)h2 | ((uint32_t)h3 << 16);
            }
            sts128(sb + A_OFF(st) + base + h * 32,      hw[0], hw[1], hw[2], hw[3]);
            sts128(sb + A_OFF(st) + base + h * 32 + 16, hw[4], hw[5], hw[6], hw[7]);
        }
    };

    lds_x(0);
    sts_A(0);
    lds_x(1);
    load_B(0, 0);
    load_B(1, 1);

    for (int it = 0; it < KITER; ++it) {
        const int ast = it & 1;
        const int bst = it % 3;
        cp_wait<1>();
        __syncthreads();
        sts_A(it + 1);
        lds_x(it + 2);
        load_B(it + 2, (it + 2) % 3);

        const uint32_t aS = sb + A_OFF(ast);
        const uint32_t bS = sb + B_OFF(bst);
        // two k32 batches: 16 ldsm -> 64-mma run each
#pragma unroll
        for (int kb = 0; kb < 2; kb++) {
            uint32_t a[2][4][4], b[2][4][4];
#pragma unroll
            for (int kk = 0; kk < 2; kk++) {
                int ks = kb * 2 + kk;
#pragma unroll
                for (int mi = 0; mi < 4; mi++) {
                    uint32_t ro = (uint32_t)((wm * 64 + mi * 16 + (lane & 15)) * ROWB +
                                             ks * 32 + (lane >> 4) * 16);
                    ldsm4(a[kk][mi], aS + ro);
                }
#pragma unroll
                for (int p = 0; p < 4; p++) {
                    uint32_t bo = (uint32_t)((wn * 64 + p * 16 + (lane >> 4) * 8 + (lane & 7)) * ROWB +
                                             ks * 32 + ((lane >> 3) & 1) * 16);
                    ldsm4(b[kk][p], bS + bo);
                }
            }
#pragma unroll
            for (int kk = 0; kk < 2; kk++)
#pragma unroll
                for (int mi = 0; mi < 4; mi++)
#pragma unroll
                    for (int p = 0; p < 4; p++) {
                        mma_f16(acc[mi][2 * p],     a[kk][mi], &b[kk][p][0]);
                        mma_f16(acc[mi][2 * p + 1], a[kk][mi], &b[kk][p][2]);
                    }
        }
    }

    // ---- epilogue: relu(acc + b0) dot W1 over this CTA's 256 hidden cols ----
    float w1v[8][2], b0v[8][2];
#pragma unroll
    for (int ni = 0; ni < 8; ni++) {
        int c = nBase + wn * 64 + ni * 8 + 2 * (lane & 3);
        w1v[ni][0] = g_W1b[c];      w1v[ni][1] = g_W1b[c + 1];
        b0v[ni][0] = __ldg(b0 + c); b0v[ni][1] = __ldg(b0 + c + 1);
    }
#pragma unroll
    for (int mi = 0; mi < 4; mi++) {
        float r0 = 0.f, r1 = 0.f;
#pragma unroll
        for (int ni = 0; ni < 8; ni++) {
            r0 += fmaxf(acc[mi][ni][0] + b0v[ni][0], 0.f) * w1v[ni][0];
            r0 += fmaxf(acc[mi][ni][1] + b0v[ni][1], 0.f) * w1v[ni][1];
            r1 += fmaxf(acc[mi][ni][2] + b0v[ni][0], 0.f) * w1v[ni][0];
            r1 += fmaxf(acc[mi][ni][3] + b0v[ni][1], 0.f) * w1v[ni][1];
        }
        r0 += __shfl_xor_sync(0xffffffffu, r0, 1);
        r0 += __shfl_xor_sync(0xffffffffu, r0, 2);
        r1 += __shfl_xor_sync(0xffffffffu, r1, 1);
        r1 += __shfl_xor_sync(0xffffffffu, r1, 2);
        if ((lane & 3) == 0) {
            int rr = wm * 64 + mi * 16 + (lane >> 2);
            red[rr * 4 + wn] = r0;
            red[(rr + 8) * 4 + wn] = r1;
        }
    }
    __syncthreads();
    if (tid < GBM) {
        float s = red[tid * 4] + red[tid * 4 + 1] + red[tid * 4 + 2] + red[tid * 4 + 3];
        g_partial[(size_t)colBlk * Brows + rowBase + tid] = s;
    }
}

__global__ void reduce_kernel(float* __restrict__ out, const float* __restrict__ b1,
                              int Brows) {
    int b = blockIdx.x * blockDim.x + threadIdx.x;
    if (b < Brows)
        out[b] = b1[0] + g_partial[b] + g_partial[(size_t)Brows + b];
}

extern "C" void kernel_launch(void* const* d_in, const int* in_sizes, int n_in,
                              void* d_out, int out_size) {
    const float* x  = (const float*)d_in[0];
    const float* w0 = (const float*)d_in[1];
    const float* b0 = (const float*)d_in[2];
    const float* w1 = (const float*)d_in[3];
    const float* b1 = (const float*)d_in[4];
    const float* p0 = (const float*)d_in[5];
    const float* p1 = (const float*)d_in[6];
    const float* g0 = (const float*)d_in[7];
    const float* g1 = (const float*)d_in[8];
    float* out = (float*)d_out;
    int Brows = in_sizes[0] / D_IN;
    const int nbig4 = D_H * D_IN / 4;

    const int DYN = 149504;  // A 2x18432 + B 3x36864 + red 2048
    cudaFuncSetAttribute(gemm_mma_kernel,
                         cudaFuncAttributeMaxDynamicSharedMemorySize, DYN);

    init_kernel<<<1, 32>>>();
    minmax2_kernel<<<dim3(128, 2), 256>>>(w0, g0, nbig4);
    hist2_kernel<<<dim3(128, 2), 256>>>(w0, g0, nbig4);
    scalar_kernel<<<1, 256>>>(w1, g1);
    w0_blend_mma_kernel<<<dim3(D_IN / 128, D_H / 64), 256>>>(w0, g0, p0);
    w1_blend_kernel<<<2, 256>>>(w1, g1, p1);
    gemm_mma_kernel<<<dim3(2, Brows / GBM), 256, DYN>>>(x, b0, Brows);
    reduce_kernel<<<(Brows + 255) / 256, 256>>>(out, b1, Brows);
}

// round 16
// speedup vs baseline: 1.0820x; 1.0820x over previous
#include <cuda_runtime.h>
#include <cuda_fp16.h>
#include <math.h>
#include <stdint.h>

#define D_IN 1024
#define D_H  512
#define NBINS 10
#define MAXB 65536

// ---------------- scratch (no allocations allowed) ----------------
__device__ unsigned int g_min_enc[2];
__device__ unsigned int g_max_enc[2];
__device__ int          g_hist[2][NBINS];
__device__ float        g_wglobal[2];
__device__ __align__(16) __half g_W0h[D_H * D_IN];   // blended W0, fp16
__device__ __align__(16) __half g_Xh[(size_t)MAXB * D_IN];  // x in fp16
__device__ __align__(16) float g_W1b[D_H];
__device__ __align__(16) float g_partial[2 * MAXB];

// ---------------- PTX helpers ----------------
__device__ __forceinline__ uint32_t smem_u32(const void* p) {
    uint32_t a;
    asm("{ .reg .u64 t; cvta.to.shared.u64 t, %1; cvt.u32.u64 %0, t; }"
        : "=r"(a) : "l"(p));
    return a;
}
__device__ __forceinline__ void cp16(uint32_t dst, const void* src) {
    asm volatile("cp.async.cg.shared.global [%0], [%1], 16;"
                 :: "r"(dst), "l"(src) : "memory");
}
__device__ __forceinline__ void cp_commit() {
    asm volatile("cp.async.commit_group;" ::: "memory");
}
template <int N>
__device__ __forceinline__ void cp_wait() {
    asm volatile("cp.async.wait_group %0;" :: "n"(N) : "memory");
}
__device__ __forceinline__ void ldsm4(uint32_t* r, uint32_t addr) {
    asm volatile("ldmatrix.sync.aligned.m8n8.x4.shared.b16 {%0,%1,%2,%3}, [%4];"
                 : "=r"(r[0]), "=r"(r[1]), "=r"(r[2]), "=r"(r[3]) : "r"(addr));
}
__device__ __forceinline__ void mma_f16(float* c, const uint32_t* a,
                                        const uint32_t* b) {
    asm volatile(
        "mma.sync.aligned.m16n8k16.row.col.f32.f16.f16.f32 "
        "{%0,%1,%2,%3}, {%4,%5,%6,%7}, {%8,%9}, {%0,%1,%2,%3};"
        : "+f"(c[0]), "+f"(c[1]), "+f"(c[2]), "+f"(c[3])
        : "r"(a[0]), "r"(a[1]), "r"(a[2]), "r"(a[3]), "r"(b[0]), "r"(b[1]));
}
__device__ __forceinline__ void sts128(uint32_t addr, uint32_t a, uint32_t b,
                                       uint32_t c, uint32_t d) {
    asm volatile("st.shared.v4.b32 [%0], {%1,%2,%3,%4};"
                 :: "r"(addr), "r"(a), "r"(b), "r"(c), "r"(d) : "memory");
}

// ---------------- entropy path (exact jnp half-open bins) ----------
__device__ __forceinline__ unsigned int enc_f(float f) {
    unsigned int u = __float_as_uint(f);
    return (u & 0x80000000u) ? ~u : (u | 0x80000000u);
}
__device__ __forceinline__ float dec_f(unsigned int u) {
    u = (u & 0x80000000u) ? (u ^ 0x80000000u) : ~u;
    return __uint_as_float(u);
}

__global__ void init_kernel() {
    int t = threadIdx.x;
    if (t < 2) { g_min_enc[t] = 0xFFFFFFFFu; g_max_enc[t] = 0u; }
    if (t < 2 * NBINS) g_hist[t / NBINS][t % NBINS] = 0;
}

// x fp32 -> fp16 (pure DRAM-bound; removes all cvt work from the GEMM)
__global__ void split_x_kernel(const float4* __restrict__ x, int n8) {
    int i = blockIdx.x * blockDim.x + threadIdx.x;
    if (i >= n8) return;
    float4 v0 = x[2 * i], v1 = x[2 * i + 1];
    __half2 h0 = __floats2half2_rn(v0.x, v0.y);
    __half2 h1 = __floats2half2_rn(v0.z, v0.w);
    __half2 h2 = __floats2half2_rn(v1.x, v1.y);
    __half2 h3 = __floats2half2_rn(v1.z, v1.w);
    uint4 o;
    o.x = *(uint32_t*)&h0; o.y = *(uint32_t*)&h1;
    o.z = *(uint32_t*)&h2; o.w = *(uint32_t*)&h3;
    ((uint4*)g_Xh)[i] = o;
}

__global__ void minmax2_kernel(const float* __restrict__ w0,
                               const float* __restrict__ g0, int n4) {
    int slot = blockIdx.y;
    const float4* p = (const float4*)(slot ? g0 : w0);
    unsigned int mn = 0xFFFFFFFFu, mx = 0u;
    int stride = gridDim.x * blockDim.x;
    for (int i = blockIdx.x * blockDim.x + threadIdx.x; i < n4; i += stride) {
        float4 v = p[i];
        unsigned int e0 = enc_f(v.x), e1 = enc_f(v.y);
        unsigned int e2 = enc_f(v.z), e3 = enc_f(v.w);
        mn = min(min(mn, e0), min(e1, min(e2, e3)));
        mx = max(max(mx, e0), max(e1, max(e2, e3)));
    }
#pragma unroll
    for (int o = 16; o; o >>= 1) {
        mn = min(mn, __shfl_down_sync(0xffffffffu, mn, o));
        mx = max(mx, __shfl_down_sync(0xffffffffu, mx, o));
    }
    __shared__ unsigned int smn[8], smx[8];
    int w = threadIdx.x >> 5, l = threadIdx.x & 31;
    if (l == 0) { smn[w] = mn; smx[w] = mx; }
    __syncthreads();
    if (threadIdx.x == 0) {
        int nw = blockDim.x >> 5;
        for (int i = 1; i < nw; i++) { mn = min(mn, smn[i]); mx = max(mx, smx[i]); }
        atomicMin(&g_min_enc[slot], mn);
        atomicMax(&g_max_enc[slot], mx);
    }
}

__global__ void hist2_kernel(const float* __restrict__ w0,
                             const float* __restrict__ g0, int n4) {
    int slot = blockIdx.y;
    const float4* p = (const float4*)(slot ? g0 : w0);
    __shared__ int sh[NBINS];
    if (threadIdx.x < NBINS) sh[threadIdx.x] = 0;
    __syncthreads();
    float lo = dec_f(g_min_enc[slot]);
    float hi = dec_f(g_max_enc[slot]);
    float scale = __fdiv_rn(__fsub_rn(hi, lo), 10.0f);
    float inv = 1.0f / scale;
    int stride = gridDim.x * blockDim.x;
    for (int i = blockIdx.x * blockDim.x + threadIdx.x; i < n4; i += stride) {
        float4 q = p[i];
        float vv[4] = {q.x, q.y, q.z, q.w};
#pragma unroll
        for (int e = 0; e < 4; e++) {
            float v = vv[e];
            int bc = (int)((v - lo) * inv);
            int b0 = max(bc - 1, 0), b1 = min(bc + 1, NBINS - 1);
            for (int b = b0; b <= b1; b++) {
                float lower = __fadd_rn(lo, __fmul_rn((float)b, scale));
                float upper = __fadd_rn(lo, __fmul_rn((float)(b + 1), scale));
                if (v >= lower && v < upper) { atomicAdd(&sh[b], 1); break; }
            }
        }
    }
    __syncthreads();
    if (threadIdx.x < NBINS) atomicAdd(&g_hist[slot][threadIdx.x], sh[threadIdx.x]);
}

__global__ void scalar_kernel(const float* __restrict__ w1,
                              const float* __restrict__ g1) {
    __shared__ unsigned int smn[2], smx[2];
    __shared__ int shist[2][NBINS];
    __shared__ float sH[2];
    int tid = threadIdx.x;  // 256 threads
    if (tid < 2) { smn[tid] = 0xFFFFFFFFu; smx[tid] = 0u; }
    if (tid < 2 * NBINS) shist[tid / NBINS][tid % NBINS] = 0;
    __syncthreads();
    const float* arr[2] = {w1, g1};
    for (int a = 0; a < 2; a++) {
        float v0 = arr[a][tid], v1 = arr[a][tid + 256];
        unsigned int mn = min(enc_f(v0), enc_f(v1));
        unsigned int mx = max(enc_f(v0), enc_f(v1));
#pragma unroll
        for (int o = 16; o; o >>= 1) {
            mn = min(mn, __shfl_down_sync(0xffffffffu, mn, o));
            mx = max(mx, __shfl_down_sync(0xffffffffu, mx, o));
        }
        if ((tid & 31) == 0) { atomicMin(&smn[a], mn); atomicMax(&smx[a], mx); }
    }
    __syncthreads();
    for (int a = 0; a < 2; a++) {
        float lo = dec_f(smn[a]), hi = dec_f(smx[a]);
        float scale = __fdiv_rn(__fsub_rn(hi, lo), 10.0f);
#pragma unroll
        for (int e = 0; e < 2; e++) {
            float v = arr[a][tid + e * 256];
#pragma unroll
            for (int b = 0; b < NBINS; b++) {
                float lower = __fadd_rn(lo, __fmul_rn((float)b, scale));
                float upper = __fadd_rn(lo, __fmul_rn((float)(b + 1), scale));
                if (v >= lower && v < upper) { atomicAdd(&shist[a][b], 1); break; }
            }
        }
    }
    __syncthreads();
    if (tid == 0) {
        const float API = 0.12732395447351627f;  // 0.4/pi
        float Hbig[2];
        for (int a = 0; a < 2; a++) {
            float h = 0.f;
            for (int b = 0; b < NBINS; b++) {
                float pp = (float)g_hist[a][b] / (float)(D_H * D_IN);
                if (pp > 0.f) h += -pp * logf(pp);
            }
            Hbig[a] = h;
        }
        g_wglobal[0] = API * atanf(500.0f * (Hbig[0] - Hbig[1])) + 0.5f;
        for (int a = 0; a < 2; a++) {
            float h = 0.f;
            for (int b = 0; b < NBINS; b++) {
                float pp = (float)shist[a][b] / (float)D_H;
                if (pp > 0.f) h += -pp * logf(pp);
            }
            sH[a] = h;
        }
        g_wglobal[1] = API * atanf(500.0f * (sH[0] - sH[1])) + 0.5f;
    }
}

__device__ __forceinline__ float blend_one(float base, float graft, float d, float wg) {
    float wl = 1.0f / (1.0f + expf(-d));
    float wb = wg * (1.0f - expf(-wg * wl));
    float og = 1.0f - wg;
    float wgf = og * (1.0f - expf(-og * (1.0f - wl)));
    float s = 1.0f / (1.0f + expf(wgf - wb));  // softmax pair == sigmoid(diff)
    return base * s + graft * (1.0f - s);
}

// ---------- w0 blend via fp16 mma (validated R9) -------------------------
#define WBROWB 80
__global__ __launch_bounds__(256) void w0_blend_mma_kernel(
    const float* __restrict__ w0, const float* __restrict__ g0,
    const float* __restrict__ p0) {
    __shared__ __align__(16) __half sA[2][64 * 40];
    __shared__ __align__(16) __half sB[2][128 * 40];
    const int tid = threadIdx.x;
    const int wid = tid >> 5, lane = tid & 31;
    const int wm = wid >> 2;
    const int wn = wid & 3;
    const int rowBase = blockIdx.y * 64;
    const int colBase = blockIdx.x * 128;
    const uint32_t sAu = smem_u32(&sA[0][0]);
    const uint32_t sBu = smem_u32(&sB[0][0]);

    const int ar = tid >> 2, agr = tid & 3;
    const int br = tid >> 1, bh = tid & 1;

    float4 aw[2], ag[2], bp[4];
    float acc[2][4][4] = {};

    auto lds = [&](int it) {
        if (it < 32) {
            const float* wr = w0 + (size_t)(rowBase + ar) * D_IN + it * 32 + agr * 8;
            const float* gr = g0 + (size_t)(rowBase + ar) * D_IN + it * 32 + agr * 8;
            const float* pr = p0 + (size_t)(colBase + br) * D_IN + it * 32 + bh * 16;
#pragma unroll
            for (int j = 0; j < 2; j++) {
                aw[j] = *(const float4*)(wr + j * 4);
                ag[j] = *(const float4*)(gr + j * 4);
            }
#pragma unroll
            for (int j = 0; j < 4; j++) bp[j] = *(const float4*)(pr + j * 4);
        }
    };
    auto sts = [&](int it) {
        if (it >= 32) return;
        int st = it & 1;
        uint32_t wa[4];
#pragma unroll
        for (int j = 0; j < 2; j++) {
            float d0 = fabsf(aw[j].x - ag[j].x), d1 = fabsf(aw[j].y - ag[j].y);
            float d2 = fabsf(aw[j].z - ag[j].z), d3 = fabsf(aw[j].w - ag[j].w);
            unsigned short h0 = __half_as_ushort(__float2half_rn(d0));
            unsigned short h1 = __half_as_ushort(__float2half_rn(d1));
            unsigned short h2 = __half_as_ushort(__float2half_rn(d2));
            unsigned short h3 = __half_as_ushort(__float2half_rn(d3));
            wa[2 * j]     = (uint32_t)h0 | ((uint32_t)h1 << 16);
            wa[2 * j + 1] = (uint32_t)h2 | ((uint32_t)h3 << 16);
        }
        sts128(sAu + (uint32_t)(st * 5120 + ar * WBROWB + agr * 16),
               wa[0], wa[1], wa[2], wa[3]);
        uint32_t bw[8];
#pragma unroll
        for (int j = 0; j < 4; j++) {
            unsigned short h0 = __half_as_ushort(__float2half_rn(bp[j].x));
            unsigned short h1 = __half_as_ushort(__float2half_rn(bp[j].y));
            unsigned short h2 = __half_as_ushort(__float2half_rn(bp[j].z));
            unsigned short h3 = __half_as_ushort(__float2half_rn(bp[j].w));
            bw[2 * j]     = (uint32_t)h0 | ((uint32_t)h1 << 16);
            bw[2 * j + 1] = (uint32_t)h2 | ((uint32_t)h3 << 16);
        }
        uint32_t bb = sBu + (uint32_t)(st * 10240 + br * WBROWB + bh * 32);
        sts128(bb,      bw[0], bw[1], bw[2], bw[3]);
        sts128(bb + 16, bw[4], bw[5], bw[6], bw[7]);
    };

    lds(0); sts(0); lds(1);
    for (int it = 0; it < 32; ++it) {
        const int st = it & 1;
        __syncthreads();
        sts(it + 1);
        lds(it + 2);
#pragma unroll
        for (int ks = 0; ks < 2; ks++) {
            uint32_t a[2][4], b[2][4];
#pragma unroll
            for (int mi = 0; mi < 2; mi++) {
                uint32_t ro = (uint32_t)(st * 5120 +
                    (wm * 32 + mi * 16 + (lane & 15)) * WBROWB +
                    ks * 32 + (lane >> 4) * 16);
                ldsm4(a[mi], sAu + ro);
            }
#pragma unroll
            for (int p = 0; p < 2; p++) {
                uint32_t bo = (uint32_t)(st * 10240 +
                    (wn * 32 + p * 16 + (lane >> 4) * 8 + (lane & 7)) * WBROWB +
                    ks * 32 + ((lane >> 3) & 1) * 16);
                ldsm4(b[p], sBu + bo);
            }
#pragma unroll
            for (int mi = 0; mi < 2; mi++)
#pragma unroll
                for (int p = 0; p < 2; p++) {
                    mma_f16(acc[mi][2 * p],     a[mi], &b[p][0]);
                    mma_f16(acc[mi][2 * p + 1], a[mi], &b[p][2]);
                }
        }
    }

    float wg = g_wglobal[0];
#pragma unroll
    for (int mi = 0; mi < 2; mi++)
#pragma unroll
        for (int ni = 0; ni < 4; ni++) {
            int col = colBase + wn * 32 + ni * 8 + 2 * (lane & 3);
#pragma unroll
            for (int rh = 0; rh < 2; rh++) {
                int o = rowBase + wm * 32 + mi * 16 + (lane >> 2) + rh * 8;
                size_t base = (size_t)o * D_IN + col;
                float v0 = blend_one(w0[base], g0[base], acc[mi][ni][2 * rh], wg);
                float v1 = blend_one(w0[base + 1], g0[base + 1],
                                     acc[mi][ni][2 * rh + 1], wg);
                __half2 h2v = __floats2half2_rn(v0, v1);
                *(__half2*)(g_W0h + base) = h2v;
            }
        }
}

__global__ void w1_blend_kernel(const float* __restrict__ w1,
                                const float* __restrict__ g1,
                                const float* __restrict__ p1) {
    int i = blockIdx.x * blockDim.x + threadIdx.x;
    if (i >= D_H) return;
    float d = 0.f;
    for (int k = 0; k < D_H; k++) d += fabsf(w1[k] - g1[k]) * p1[i * D_H + k];
    g_W1b[i] = blend_one(w1[i], g1[i], d, g_wglobal[1]);
}

// ---------------- main GEMM: pure cp.async A+B, no in-kernel converts -----
#define GBM 128
#define GBN 256
#define GBK 64
#define KITER (D_IN / GBK)   // 16
#define ROWB 144             // 64 fp16 = 128B + 16B pad

#define A_OFF(st) ((uint32_t)((st) * 18432))
#define B_OFF(st) ((uint32_t)(55296 + (st) * 36864))
#define RED_OFF 165888u

__global__ __launch_bounds__(256, 1) void gemm_mma_kernel(
    const float* __restrict__ b0, int Brows) {
    extern __shared__ char dsm[];
    const uint32_t sb = smem_u32(dsm);
    float* red = (float*)(dsm + RED_OFF);  // [128][4]

    const int tid = threadIdx.x;
    const int wid = tid >> 5, lane = tid & 31;
    const int wm = wid >> 2;       // 0..1 -> 64-row warp tile
    const int wn = wid & 3;        // 0..3 -> 64-col warp tile
    const int colBlk = blockIdx.x;            // 0..1
    const int rowBase = blockIdx.y * GBM;
    const int nBase = colBlk * GBN;

    float acc[4][8][4] = {};

    auto load_tiles = [&](int it, int st) {
        if (it < KITER) {
            const __half* srcA = g_Xh + (size_t)rowBase * D_IN + it * GBK;
            const __half* srcB = g_W0h + (size_t)nBase * D_IN + it * GBK;
            // A: 128 rows x 8 granules = 1024 jobs (4 per thread)
#pragma unroll
            for (int i = 0; i < 4; i++) {
                int q = tid + i * 256;
                int r = q >> 3, g = q & 7;
                uint32_t doff = (uint32_t)(r * ROWB + g * 16);
                cp16(sb + A_OFF(st) + doff, srcA + (size_t)r * D_IN + g * 8);
            }
            // B: 256 rows x 8 granules = 2048 jobs (8 per thread)
#pragma unroll
            for (int i = 0; i < 8; i++) {
                int q = tid + i * 256;
                int r = q >> 3, g = q & 7;
                uint32_t doff = (uint32_t)(r * ROWB + g * 16);
                cp16(sb + B_OFF(st) + doff, srcB + (size_t)r * D_IN + g * 8);
            }
        }
        cp_commit();
    };

    load_tiles(0, 0);
    load_tiles(1, 1);

    for (int it = 0; it < KITER; ++it) {
        const int st = it % 3;
        cp_wait<1>();
        __syncthreads();
        load_tiles(it + 2, (it + 2) % 3);

        const uint32_t aS = sb + A_OFF(st);
        const uint32_t bS = sb + B_OFF(st);
#pragma unroll
        for (int ks = 0; ks < 4; ks++) {
            uint32_t a[4][4], b[4][4];
#pragma unroll
            for (int mi = 0; mi < 4; mi++) {
                uint32_t ro = (uint32_t)((wm * 64 + mi * 16 + (lane & 15)) * ROWB +
                                         ks * 32 + (lane >> 4) * 16);
                ldsm4(a[mi], aS + ro);
            }
#pragma unroll
            for (int p = 0; p < 4; p++) {
                uint32_t bo = (uint32_t)((wn * 64 + p * 16 + (lane >> 4) * 8 + (lane & 7)) * ROWB +
                                         ks * 32 + ((lane >> 3) & 1) * 16);
                ldsm4(b[p], bS + bo);
            }
#pragma unroll
            for (int mi = 0; mi < 4; mi++)
#pragma unroll
                for (int p = 0; p < 4; p++) {
                    mma_f16(acc[mi][2 * p],     a[mi], &b[p][0]);
                    mma_f16(acc[mi][2 * p + 1], a[mi], &b[p][2]);
                }
        }
    }

    // ---- epilogue: relu(acc + b0) dot W1 over this CTA's 256 hidden cols ----
    float w1v[8][2], b0v[8][2];
#pragma unroll
    for (int ni = 0; ni < 8; ni++) {
        int c = nBase + wn * 64 + ni * 8 + 2 * (lane & 3);
        w1v[ni][0] = g_W1b[c];      w1v[ni][1] = g_W1b[c + 1];
        b0v[ni][0] = __ldg(b0 + c); b0v[ni][1] = __ldg(b0 + c + 1);
    }
#pragma unroll
    for (int mi = 0; mi < 4; mi++) {
        float r0 = 0.f, r1 = 0.f;
#pragma unroll
        for (int ni = 0; ni < 8; ni++) {
            r0 += fmaxf(acc[mi][ni][0] + b0v[ni][0], 0.f) * w1v[ni][0];
            r0 += fmaxf(acc[mi][ni][1] + b0v[ni][1], 0.f) * w1v[ni][1];
            r1 += fmaxf(acc[mi][ni][2] + b0v[ni][0], 0.f) * w1v[ni][0];
            r1 += fmaxf(acc[mi][ni][3] + b0v[ni][1], 0.f) * w1v[ni][1];
        }
        r0 += __shfl_xor_sync(0xffffffffu, r0, 1);
        r0 += __shfl_xor_sync(0xffffffffu, r0, 2);
        r1 += __shfl_xor_sync(0xffffffffu, r1, 1);
        r1 += __shfl_xor_sync(0xffffffffu, r1, 2);
        if ((lane & 3) == 0) {
            int rr = wm * 64 + mi * 16 + (lane >> 2);
            red[rr * 4 + wn] = r0;
            red[(rr + 8) * 4 + wn] = r1;
        }
    }
    __syncthreads();
    if (tid < GBM) {
        float s = red[tid * 4] + red[tid * 4 + 1] + red[tid * 4 + 2] + red[tid * 4 + 3];
        g_partial[(size_t)colBlk * Brows + rowBase + tid] = s;
    }
}

__global__ void reduce_kernel(float* __restrict__ out, const float* __restrict__ b1,
                              int Brows) {
    int b = blockIdx.x * blockDim.x + threadIdx.x;
    if (b < Brows)
        out[b] = b1[0] + g_partial[b] + g_partial[(size_t)Brows + b];
}

extern "C" void kernel_launch(void* const* d_in, const int* in_sizes, int n_in,
                              void* d_out, int out_size) {
    const float* x  = (const float*)d_in[0];
    const float* w0 = (const float*)d_in[1];
    const float* b0 = (const float*)d_in[2];
    const float* w1 = (const float*)d_in[3];
    const float* b1 = (const float*)d_in[4];
    const float* p0 = (const float*)d_in[5];
    const float* p1 = (const float*)d_in[6];
    const float* g0 = (const float*)d_in[7];
    const float* g1 = (const float*)d_in[8];
    float* out = (float*)d_out;
    int Brows = in_sizes[0] / D_IN;
    const int nbig4 = D_H * D_IN / 4;
    int n8 = Brows * D_IN / 8;

    const int DYN = 167936;  // A 3x18432 + B 3x36864 + red 2048
    cudaFuncSetAttribute(gemm_mma_kernel,
                         cudaFuncAttributeMaxDynamicSharedMemorySize, DYN);

    init_kernel<<<1, 32>>>();
    split_x_kernel<<<(n8 + 255) / 256, 256>>>((const float4*)x, n8);
    minmax2_kernel<<<dim3(128, 2), 256>>>(w0, g0, nbig4);
    hist2_kernel<<<dim3(128, 2), 256>>>(w0, g0, nbig4);
    scalar_kernel<<<1, 256>>>(w1, g1);
    w0_blend_mma_kernel<<<dim3(D_IN / 128, D_H / 64), 256>>>(w0, g0, p0);
    w1_blend_kernel<<<2, 256>>>(w1, g1, p1);
    gemm_mma_kernel<<<dim3(2, Brows / GBM), 256, DYN>>>(b0, Brows);
    reduce_kernel<<<(Brows + 255) / 256, 256>>>(out, b1, Brows);
}

// round 17
// speedup vs baseline: 1.0893x; 1.0067x over previous
#include <cuda_runtime.h>
#include <cuda_fp16.h>
#include <math.h>
#include <stdint.h>

#define D_IN 1024
#define D_H  512
#define NBINS 10
#define MAXB 65536

// ---------------- scratch (no allocations allowed) ----------------
__device__ unsigned int g_min_enc[2];
__device__ unsigned int g_max_enc[2];
__device__ int          g_hist[2][NBINS];
__device__ float        g_wglobal[2];
__device__ __align__(16) __half g_W0h[D_H * D_IN];   // blended W0, fp16
__device__ __align__(16) __half g_Xh[(size_t)MAXB * D_IN];  // x in fp16
__device__ __align__(16) float g_W1b[D_H];
__device__ __align__(16) float g_partial[2 * MAXB];

// ---------------- PTX helpers ----------------
__device__ __forceinline__ uint32_t smem_u32(const void* p) {
    uint32_t a;
    asm("{ .reg .u64 t; cvta.to.shared.u64 t, %1; cvt.u32.u64 %0, t; }"
        : "=r"(a) : "l"(p));
    return a;
}
__device__ __forceinline__ void cp16(uint32_t dst, const void* src) {
    asm volatile("cp.async.cg.shared.global [%0], [%1], 16;"
                 :: "r"(dst), "l"(src) : "memory");
}
__device__ __forceinline__ void cp_commit() {
    asm volatile("cp.async.commit_group;" ::: "memory");
}
template <int N>
__device__ __forceinline__ void cp_wait() {
    asm volatile("cp.async.wait_group %0;" :: "n"(N) : "memory");
}
__device__ __forceinline__ void ldsm4(uint32_t* r, uint32_t addr) {
    asm volatile("ldmatrix.sync.aligned.m8n8.x4.shared.b16 {%0,%1,%2,%3}, [%4];"
                 : "=r"(r[0]), "=r"(r[1]), "=r"(r[2]), "=r"(r[3]) : "r"(addr));
}
__device__ __forceinline__ void mma_f16(float* c, const uint32_t* a,
                                        const uint32_t* b) {
    asm volatile(
        "mma.sync.aligned.m16n8k16.row.col.f32.f16.f16.f32 "
        "{%0,%1,%2,%3}, {%4,%5,%6,%7}, {%8,%9}, {%0,%1,%2,%3};"
        : "+f"(c[0]), "+f"(c[1]), "+f"(c[2]), "+f"(c[3])
        : "r"(a[0]), "r"(a[1]), "r"(a[2]), "r"(a[3]), "r"(b[0]), "r"(b[1]));
}
__device__ __forceinline__ void sts128(uint32_t addr, uint32_t a, uint32_t b,
                                       uint32_t c, uint32_t d) {
    asm volatile("st.shared.v4.b32 [%0], {%1,%2,%3,%4};"
                 :: "r"(addr), "r"(a), "r"(b), "r"(c), "r"(d) : "memory");
}

// ---------------- entropy path (exact jnp half-open bins) ----------
__device__ __forceinline__ unsigned int enc_f(float f) {
    unsigned int u = __float_as_uint(f);
    return (u & 0x80000000u) ? ~u : (u | 0x80000000u);
}
__device__ __forceinline__ float dec_f(unsigned int u) {
    u = (u & 0x80000000u) ? (u ^ 0x80000000u) : ~u;
    return __uint_as_float(u);
}

__global__ void init_kernel() {
    int t = threadIdx.x;
    if (t < 2) { g_min_enc[t] = 0xFFFFFFFFu; g_max_enc[t] = 0u; }
    if (t < 2 * NBINS) g_hist[t / NBINS][t % NBINS] = 0;
}

// x fp32 -> fp16 (pure DRAM-bound; overlapped with the entropy/blend chain)
__global__ void split_x_kernel(const float4* __restrict__ x, int n8) {
    int i = blockIdx.x * blockDim.x + threadIdx.x;
    if (i >= n8) return;
    float4 v0 = x[2 * i], v1 = x[2 * i + 1];
    __half2 h0 = __floats2half2_rn(v0.x, v0.y);
    __half2 h1 = __floats2half2_rn(v0.z, v0.w);
    __half2 h2 = __floats2half2_rn(v1.x, v1.y);
    __half2 h3 = __floats2half2_rn(v1.z, v1.w);
    uint4 o;
    o.x = *(uint32_t*)&h0; o.y = *(uint32_t*)&h1;
    o.z = *(uint32_t*)&h2; o.w = *(uint32_t*)&h3;
    ((uint4*)g_Xh)[i] = o;
}

__global__ void minmax2_kernel(const float* __restrict__ w0,
                               const float* __restrict__ g0, int n4) {
    int slot = blockIdx.y;
    const float4* p = (const float4*)(slot ? g0 : w0);
    unsigned int mn = 0xFFFFFFFFu, mx = 0u;
    int stride = gridDim.x * blockDim.x;
    for (int i = blockIdx.x * blockDim.x + threadIdx.x; i < n4; i += stride) {
        float4 v = p[i];
        unsigned int e0 = enc_f(v.x), e1 = enc_f(v.y);
        unsigned int e2 = enc_f(v.z), e3 = enc_f(v.w);
        mn = min(min(mn, e0), min(e1, min(e2, e3)));
        mx = max(max(mx, e0), max(e1, max(e2, e3)));
    }
#pragma unroll
    for (int o = 16; o; o >>= 1) {
        mn = min(mn, __shfl_down_sync(0xffffffffu, mn, o));
        mx = max(mx, __shfl_down_sync(0xffffffffu, mx, o));
    }
    __shared__ unsigned int smn[8], smx[8];
    int w = threadIdx.x >> 5, l = threadIdx.x & 31;
    if (l == 0) { smn[w] = mn; smx[w] = mx; }
    __syncthreads();
    if (threadIdx.x == 0) {
        int nw = blockDim.x >> 5;
        for (int i = 1; i < nw; i++) { mn = min(mn, smn[i]); mx = max(mx, smx[i]); }
        atomicMin(&g_min_enc[slot], mn);
        atomicMax(&g_max_enc[slot], mx);
    }
}

__global__ void hist2_kernel(const float* __restrict__ w0,
                             const float* __restrict__ g0, int n4) {
    int slot = blockIdx.y;
    const float4* p = (const float4*)(slot ? g0 : w0);
    __shared__ int sh[NBINS];
    if (threadIdx.x < NBINS) sh[threadIdx.x] = 0;
    __syncthreads();
    float lo = dec_f(g_min_enc[slot]);
    float hi = dec_f(g_max_enc[slot]);
    float scale = __fdiv_rn(__fsub_rn(hi, lo), 10.0f);
    float inv = 1.0f / scale;
    int stride = gridDim.x * blockDim.x;
    for (int i = blockIdx.x * blockDim.x + threadIdx.x; i < n4; i += stride) {
        float4 q = p[i];
        float vv[4] = {q.x, q.y, q.z, q.w};
#pragma unroll
        for (int e = 0; e < 4; e++) {
            float v = vv[e];
            int bc = (int)((v - lo) * inv);
            int b0 = max(bc - 1, 0), b1 = min(bc + 1, NBINS - 1);
            for (int b = b0; b <= b1; b++) {
                float lower = __fadd_rn(lo, __fmul_rn((float)b, scale));
                float upper = __fadd_rn(lo, __fmul_rn((float)(b + 1), scale));
                if (v >= lower && v < upper) { atomicAdd(&sh[b], 1); break; }
            }
        }
    }
    __syncthreads();
    if (threadIdx.x < NBINS) atomicAdd(&g_hist[slot][threadIdx.x], sh[threadIdx.x]);
}

__global__ void scalar_kernel(const float* __restrict__ w1,
                              const float* __restrict__ g1) {
    __shared__ unsigned int smn[2], smx[2];
    __shared__ int shist[2][NBINS];
    __shared__ float sH[2];
    int tid = threadIdx.x;  // 256 threads
    if (tid < 2) { smn[tid] = 0xFFFFFFFFu; smx[tid] = 0u; }
    if (tid < 2 * NBINS) shist[tid / NBINS][tid % NBINS] = 0;
    __syncthreads();
    const float* arr[2] = {w1, g1};
    for (int a = 0; a < 2; a++) {
        float v0 = arr[a][tid], v1 = arr[a][tid + 256];
        unsigned int mn = min(enc_f(v0), enc_f(v1));
        unsigned int mx = max(enc_f(v0), enc_f(v1));
#pragma unroll
        for (int o = 16; o; o >>= 1) {
            mn = min(mn, __shfl_down_sync(0xffffffffu, mn, o));
            mx = max(mx, __shfl_down_sync(0xffffffffu, mx, o));
        }
        if ((tid & 31) == 0) { atomicMin(&smn[a], mn); atomicMax(&smx[a], mx); }
    }
    __syncthreads();
    for (int a = 0; a < 2; a++) {
        float lo = dec_f(smn[a]), hi = dec_f(smx[a]);
        float scale = __fdiv_rn(__fsub_rn(hi, lo), 10.0f);
#pragma unroll
        for (int e = 0; e < 2; e++) {
            float v = arr[a][tid + e * 256];
#pragma unroll
            for (int b = 0; b < NBINS; b++) {
                float lower = __fadd_rn(lo, __fmul_rn((float)b, scale));
                float upper = __fadd_rn(lo, __fmul_rn((float)(b + 1), scale));
                if (v >= lower && v < upper) { atomicAdd(&shist[a][b], 1); break; }
            }
        }
    }
    __syncthreads();
    if (tid == 0) {
        const float API = 0.12732395447351627f;  // 0.4/pi
        float Hbig[2];
        for (int a = 0; a < 2; a++) {
            float h = 0.f;
            for (int b = 0; b < NBINS; b++) {
                float pp = (float)g_hist[a][b] / (float)(D_H * D_IN);
                if (pp > 0.f) h += -pp * logf(pp);
            }
            Hbig[a] = h;
        }
        g_wglobal[0] = API * atanf(500.0f * (Hbig[0] - Hbig[1])) + 0.5f;
        for (int a = 0; a < 2; a++) {
            float h = 0.f;
            for (int b = 0; b < NBINS; b++) {
                float pp = (float)shist[a][b] / (float)D_H;
                if (pp > 0.f) h += -pp * logf(pp);
            }
            sH[a] = h;
        }
        g_wglobal[1] = API * atanf(500.0f * (sH[0] - sH[1])) + 0.5f;
    }
}

__device__ __forceinline__ float blend_one(float base, float graft, float d, float wg) {
    float wl = 1.0f / (1.0f + expf(-d));
    float wb = wg * (1.0f - expf(-wg * wl));
    float og = 1.0f - wg;
    float wgf = og * (1.0f - expf(-og * (1.0f - wl)));
    float s = 1.0f / (1.0f + expf(wgf - wb));  // softmax pair == sigmoid(diff)
    return base * s + graft * (1.0f - s);
}

// ---------- w0 blend via fp16 mma (validated R9) -------------------------
#define WBROWB 80
__global__ __launch_bounds__(256) void w0_blend_mma_kernel(
    const float* __restrict__ w0, const float* __restrict__ g0,
    const float* __restrict__ p0) {
    __shared__ __align__(16) __half sA[2][64 * 40];
    __shared__ __align__(16) __half sB[2][128 * 40];
    const int tid = threadIdx.x;
    const int wid = tid >> 5, lane = tid & 31;
    const int wm = wid >> 2;
    const int wn = wid & 3;
    const int rowBase = blockIdx.y * 64;
    const int colBase = blockIdx.x * 128;
    const uint32_t sAu = smem_u32(&sA[0][0]);
    const uint32_t sBu = smem_u32(&sB[0][0]);

    const int ar = tid >> 2, agr = tid & 3;
    const int br = tid >> 1, bh = tid & 1;

    float4 aw[2], ag[2], bp[4];
    float acc[2][4][4] = {};

    auto lds = [&](int it) {
        if (it < 32) {
            const float* wr = w0 + (size_t)(rowBase + ar) * D_IN + it * 32 + agr * 8;
            const float* gr = g0 + (size_t)(rowBase + ar) * D_IN + it * 32 + agr * 8;
            const float* pr = p0 + (size_t)(colBase + br) * D_IN + it * 32 + bh * 16;
#pragma unroll
            for (int j = 0; j < 2; j++) {
                aw[j] = *(const float4*)(wr + j * 4);
                ag[j] = *(const float4*)(gr + j * 4);
            }
#pragma unroll
            for (int j = 0; j < 4; j++) bp[j] = *(const float4*)(pr + j * 4);
        }
    };
    auto sts = [&](int it) {
        if (it >= 32) return;
        int st = it & 1;
        uint32_t wa[4];
#pragma unroll
        for (int j = 0; j < 2; j++) {
            float d0 = fabsf(aw[j].x - ag[j].x), d1 = fabsf(aw[j].y - ag[j].y);
            float d2 = fabsf(aw[j].z - ag[j].z), d3 = fabsf(aw[j].w - ag[j].w);
            unsigned short h0 = __half_as_ushort(__float2half_rn(d0));
            unsigned short h1 = __half_as_ushort(__float2half_rn(d1));
            unsigned short h2 = __half_as_ushort(__float2half_rn(d2));
            unsigned short h3 = __half_as_ushort(__float2half_rn(d3));
            wa[2 * j]     = (uint32_t)h0 | ((uint32_t)h1 << 16);
            wa[2 * j + 1] = (uint32_t)h2 | ((uint32_t)h3 << 16);
        }
        sts128(sAu + (uint32_t)(st * 5120 + ar * WBROWB + agr * 16),
               wa[0], wa[1], wa[2], wa[3]);
        uint32_t bw[8];
#pragma unroll
        for (int j = 0; j < 4; j++) {
            unsigned short h0 = __half_as_ushort(__float2half_rn(bp[j].x));
            unsigned short h1 = __half_as_ushort(__float2half_rn(bp[j].y));
            unsigned short h2 = __half_as_ushort(__float2half_rn(bp[j].z));
            unsigned short h3 = __half_as_ushort(__float2half_rn(bp[j].w));
            bw[2 * j]     = (uint32_t)h0 | ((uint32_t)h1 << 16);
            bw[2 * j + 1] = (uint32_t)h2 | ((uint32_t)h3 << 16);
        }
        uint32_t bb = sBu + (uint32_t)(st * 10240 + br * WBROWB + bh * 32);
        sts128(bb,      bw[0], bw[1], bw[2], bw[3]);
        sts128(bb + 16, bw[4], bw[5], bw[6], bw[7]);
    };

    lds(0); sts(0); lds(1);
    for (int it = 0; it < 32; ++it) {
        const int st = it & 1;
        __syncthreads();
        sts(it + 1);
        lds(it + 2);
#pragma unroll
        for (int ks = 0; ks < 2; ks++) {
            uint32_t a[2][4], b[2][4];
#pragma unroll
            for (int mi = 0; mi < 2; mi++) {
                uint32_t ro = (uint32_t)(st * 5120 +
                    (wm * 32 + mi * 16 + (lane & 15)) * WBROWB +
                    ks * 32 + (lane >> 4) * 16);
                ldsm4(a[mi], sAu + ro);
            }
#pragma unroll
            for (int p = 0; p < 2; p++) {
                uint32_t bo = (uint32_t)(st * 10240 +
                    (wn * 32 + p * 16 + (lane >> 4) * 8 + (lane & 7)) * WBROWB +
                    ks * 32 + ((lane >> 3) & 1) * 16);
                ldsm4(b[p], sBu + bo);
            }
#pragma unroll
            for (int mi = 0; mi < 2; mi++)
#pragma unroll
                for (int p = 0; p < 2; p++) {
                    mma_f16(acc[mi][2 * p],     a[mi], &b[p][0]);
                    mma_f16(acc[mi][2 * p + 1], a[mi], &b[p][2]);
                }
        }
    }

    float wg = g_wglobal[0];
#pragma unroll
    for (int mi = 0; mi < 2; mi++)
#pragma unroll
        for (int ni = 0; ni < 4; ni++) {
            int col = colBase + wn * 32 + ni * 8 + 2 * (lane & 3);
#pragma unroll
            for (int rh = 0; rh < 2; rh++) {
                int o = rowBase + wm * 32 + mi * 16 + (lane >> 2) + rh * 8;
                size_t base = (size_t)o * D_IN + col;
                float v0 = blend_one(w0[base], g0[base], acc[mi][ni][2 * rh], wg);
                float v1 = blend_one(w0[base + 1], g0[base + 1],
                                     acc[mi][ni][2 * rh + 1], wg);
                __half2 h2v = __floats2half2_rn(v0, v1);
                *(__half2*)(g_W0h + base) = h2v;
            }
        }
}

__global__ void w1_blend_kernel(const float* __restrict__ w1,
                                const float* __restrict__ g1,
                                const float* __restrict__ p1) {
    int i = blockIdx.x * blockDim.x + threadIdx.x;
    if (i >= D_H) return;
    float d = 0.f;
    for (int k = 0; k < D_H; k++) d += fabsf(w1[k] - g1[k]) * p1[i * D_H + k];
    g_W1b[i] = blend_one(w1[i], g1[i], d, g_wglobal[1]);
}

// ---------------- main GEMM: pure cp.async A+B (validated R16) ------------
#define GBM 128
#define GBN 256
#define GBK 64
#define KITER (D_IN / GBK)   // 16
#define ROWB 144             // 64 fp16 = 128B + 16B pad

#define A_OFF(st) ((uint32_t)((st) * 18432))
#define B_OFF(st) ((uint32_t)(55296 + (st) * 36864))
#define RED_OFF 165888u

__global__ __launch_bounds__(256, 1) void gemm_mma_kernel(
    const float* __restrict__ b0, int Brows) {
    extern __shared__ char dsm[];
    const uint32_t sb = smem_u32(dsm);
    float* red = (float*)(dsm + RED_OFF);  // [128][4]

    const int tid = threadIdx.x;
    const int wid = tid >> 5, lane = tid & 31;
    const int wm = wid >> 2;       // 0..1 -> 64-row warp tile
    const int wn = wid & 3;        // 0..3 -> 64-col warp tile
    const int colBlk = blockIdx.x;            // 0..1
    const int rowBase = blockIdx.y * GBM;
    const int nBase = colBlk * GBN;

    float acc[4][8][4] = {};

    auto load_tiles = [&](int it, int st) {
        if (it < KITER) {
            const __half* srcA = g_Xh + (size_t)rowBase * D_IN + it * GBK;
            const __half* srcB = g_W0h + (size_t)nBase * D_IN + it * GBK;
#pragma unroll
            for (int i = 0; i < 4; i++) {
                int q = tid + i * 256;
                int r = q >> 3, g = q & 7;
                uint32_t doff = (uint32_t)(r * ROWB + g * 16);
                cp16(sb + A_OFF(st) + doff, srcA + (size_t)r * D_IN + g * 8);
            }
#pragma unroll
            for (int i = 0; i < 8; i++) {
                int q = tid + i * 256;
                int r = q >> 3, g = q & 7;
                uint32_t doff = (uint32_t)(r * ROWB + g * 16);
                cp16(sb + B_OFF(st) + doff, srcB + (size_t)r * D_IN + g * 8);
            }
        }
        cp_commit();
    };

    load_tiles(0, 0);
    load_tiles(1, 1);

    for (int it = 0; it < KITER; ++it) {
        const int st = it % 3;
        cp_wait<1>();
        __syncthreads();
        load_tiles(it + 2, (it + 2) % 3);

        const uint32_t aS = sb + A_OFF(st);
        const uint32_t bS = sb + B_OFF(st);
#pragma unroll
        for (int ks = 0; ks < 4; ks++) {
            uint32_t a[4][4], b[4][4];
#pragma unroll
            for (int mi = 0; mi < 4; mi++) {
                uint32_t ro = (uint32_t)((wm * 64 + mi * 16 + (lane & 15)) * ROWB +
                                         ks * 32 + (lane >> 4) * 16);
                ldsm4(a[mi], aS + ro);
            }
#pragma unroll
            for (int p = 0; p < 4; p++) {
                uint32_t bo = (uint32_t)((wn * 64 + p * 16 + (lane >> 4) * 8 + (lane & 7)) * ROWB +
                                         ks * 32 + ((lane >> 3) & 1) * 16);
                ldsm4(b[p], bS + bo);
            }
#pragma unroll
            for (int mi = 0; mi < 4; mi++)
#pragma unroll
                for (int p = 0; p < 4; p++) {
                    mma_f16(acc[mi][2 * p],     a[mi], &b[p][0]);
                    mma_f16(acc[mi][2 * p + 1], a[mi], &b[p][2]);
                }
        }
    }

    // ---- epilogue: relu(acc + b0) dot W1 over this CTA's 256 hidden cols ----
    float w1v[8][2], b0v[8][2];
#pragma unroll
    for (int ni = 0; ni < 8; ni++) {
        int c = nBase + wn * 64 + ni * 8 + 2 * (lane & 3);
        w1v[ni][0] = g_W1b[c];      w1v[ni][1] = g_W1b[c + 1];
        b0v[ni][0] = __ldg(b0 + c); b0v[ni][1] = __ldg(b0 + c + 1);
    }
#pragma unroll
    for (int mi = 0; mi < 4; mi++) {
        float r0 = 0.f, r1 = 0.f;
#pragma unroll
        for (int ni = 0; ni < 8; ni++) {
            r0 += fmaxf(acc[mi][ni][0] + b0v[ni][0], 0.f) * w1v[ni][0];
            r0 += fmaxf(acc[mi][ni][1] + b0v[ni][1], 0.f) * w1v[ni][1];
            r1 += fmaxf(acc[mi][ni][2] + b0v[ni][0], 0.f) * w1v[ni][0];
            r1 += fmaxf(acc[mi][ni][3] + b0v[ni][1], 0.f) * w1v[ni][1];
        }
        r0 += __shfl_xor_sync(0xffffffffu, r0, 1);
        r0 += __shfl_xor_sync(0xffffffffu, r0, 2);
        r1 += __shfl_xor_sync(0xffffffffu, r1, 1);
        r1 += __shfl_xor_sync(0xffffffffu, r1, 2);
        if ((lane & 3) == 0) {
            int rr = wm * 64 + mi * 16 + (lane >> 2);
            red[rr * 4 + wn] = r0;
            red[(rr + 8) * 4 + wn] = r1;
        }
    }
    __syncthreads();
    if (tid < GBM) {
        float s = red[tid * 4] + red[tid * 4 + 1] + red[tid * 4 + 2] + red[tid * 4 + 3];
        g_partial[(size_t)colBlk * Brows + rowBase + tid] = s;
    }
}

__global__ void reduce_kernel(float* __restrict__ out, const float* __restrict__ b1,
                              int Brows) {
    int b = blockIdx.x * blockDim.x + threadIdx.x;
    if (b < Brows)
        out[b] = b1[0] + g_partial[b] + g_partial[(size_t)Brows + b];
}

extern "C" void kernel_launch(void* const* d_in, const int* in_sizes, int n_in,
                              void* d_out, int out_size) {
    const float* x  = (const float*)d_in[0];
    const float* w0 = (const float*)d_in[1];
    const float* b0 = (const float*)d_in[2];
    const float* w1 = (const float*)d_in[3];
    const float* b1 = (const float*)d_in[4];
    const float* p0 = (const float*)d_in[5];
    const float* p1 = (const float*)d_in[6];
    const float* g0 = (const float*)d_in[7];
    const float* g1 = (const float*)d_in[8];
    float* out = (float*)d_out;
    int Brows = in_sizes[0] / D_IN;
    const int nbig4 = D_H * D_IN / 4;
    int n8 = Brows * D_IN / 8;

    const int DYN = 167936;  // A 3x18432 + B 3x36864 + red 2048
    cudaFuncSetAttribute(gemm_mma_kernel,
                         cudaFuncAttributeMaxDynamicSharedMemorySize, DYN);

    // Side stream for the independent split_x chain (cross-stream capture
    // pattern: fork via event from the main stream, join before the GEMM).
    // Host code runs only during the correctness call + the capture call;
    // graph replays do not re-execute it, so the create/destroy is not hot.
    cudaStream_t side;
    cudaEvent_t evFork, evJoin;
    cudaStreamCreateWithFlags(&side, cudaStreamNonBlocking);
    cudaEventCreateWithFlags(&evFork, cudaEventDisableTiming);
    cudaEventCreateWithFlags(&evJoin, cudaEventDisableTiming);

    cudaEventRecord(evFork, 0);
    cudaStreamWaitEvent(side, evFork, 0);
    split_x_kernel<<<(n8 + 255) / 256, 256, 0, side>>>((const float4*)x, n8);
    cudaEventRecord(evJoin, side);

    // main-stream pre-chain (independent of x)
    init_kernel<<<1, 32>>>();
    minmax2_kernel<<<dim3(128, 2), 256>>>(w0, g0, nbig4);
    hist2_kernel<<<dim3(128, 2), 256>>>(w0, g0, nbig4);
    scalar_kernel<<<1, 256>>>(w1, g1);
    w0_blend_mma_kernel<<<dim3(D_IN / 128, D_H / 64), 256>>>(w0, g0, p0);
    w1_blend_kernel<<<2, 256>>>(w1, g1, p1);

    cudaStreamWaitEvent(0, evJoin, 0);
    gemm_mma_kernel<<<dim3(2, Brows / GBM), 256, DYN>>>(b0, Brows);
    reduce_kernel<<<(Brows + 255) / 256, 256>>>(out, b1, Brows);

    cudaEventDestroy(evFork);
    cudaEventDestroy(evJoin);
    cudaStreamDestroy(side);
}